// round 1
// baseline (speedup 1.0000x reference)
#include <cuda_runtime.h>
#include <math.h>

#define NN 8192
#define CC 512
#define KK 64
#define NBLK (NN/64)   // 128 row-blocks of 64

// Scratch (device globals — no allocation allowed)
__device__ float g_phi_i[NN*KK];
__device__ float g_phi_j[NN*KK];
__device__ float g_At[CC*KK];   // [c][k] = 1/s^2          (transposed for coalesced k-reads)
__device__ float g_Bt[CC*KK];   // [c][k] = m/s^2
__device__ float g_t3[KK];      // sum_c m^2/s^2
__device__ int   g_nz[2][NBLK]; // per-64-row-block "any nonzero phi" flag (0: phi_i, 1: phi_j)

// ---------------------------------------------------------------------------
// Prep: transpose-derive A = 1/s^2, B = m/s^2, t3[k] = sum m^2/s^2
// ---------------------------------------------------------------------------
__global__ void prep_kernel(const float* __restrict__ means,
                            const float* __restrict__ scales) {
    int k = blockIdx.x;
    int t = threadIdx.x;
    float s3 = 0.f;
    for (int c = t; c < CC; c += blockDim.x) {
        float s   = scales[k*CC + c];
        float is2 = 1.0f / (s * s);
        float m   = means[k*CC + c];
        g_At[c*KK + k] = is2;
        g_Bt[c*KK + k] = m * is2;
        s3 += m * m * is2;
    }
    __shared__ float red[128];
    red[t] = s3;
    __syncthreads();
    #pragma unroll
    for (int s = 64; s > 0; s >>= 1) {
        if (t < s) red[t] += red[t + s];
        __syncthreads();
    }
    if (t == 0) g_t3[k] = red[0];
}

// ---------------------------------------------------------------------------
// Phi: per block, 64 rows x all 64 k. Factorized two-FMA inner loop:
//   dist[n,k] = -( sum_c f^2*A[c,k]  - 2*sum_c f*B[c,k]  + t3[k] )
//   phi = exp(dist) (* w[k] for the i-side)
// Also emits per-row-block nonzero flag for the GEMM zero-skip.
// ---------------------------------------------------------------------------
__global__ __launch_bounds__(256)
void phi_kernel(const float* __restrict__ f_i, const float* __restrict__ f_j,
                const float* __restrict__ weights) {
    const int isI = (blockIdx.y == 0);
    const float* __restrict__ f = isI ? f_i : f_j;
    float* __restrict__ phi = isI ? g_phi_i : g_phi_j;
    const int n0 = blockIdx.x * 64;

    __shared__ float fs [32][68];   // [c_local][n_local]
    __shared__ float f2s[32][68];
    __shared__ float As [32][64];   // [c_local][k]
    __shared__ float Bs [32][64];
    __shared__ int   s_nz;

    const int t  = threadIdx.x;
    const int kx = (t & 15) * 4;   // k base (4 k's per thread)
    const int ny = (t >> 4) * 4;   // n base (4 n's per thread)

    if (t == 0) s_nz = 0;

    float acc1[4][4], acc2[4][4];
    #pragma unroll
    for (int i = 0; i < 4; i++)
        #pragma unroll
        for (int j = 0; j < 4; j++) { acc1[i][j] = 0.f; acc2[i][j] = 0.f; }

    for (int cc = 0; cc < CC; cc += 32) {
        // load f chunk [64 rows x 32 c] transposed into smem (+ squares)
        #pragma unroll
        for (int v = 0; v < 2; v++) {
            int vid = t + v * 256;          // 0..511 float4 slots
            int row = vid >> 3;             // 8 float4 per row
            int c4  = (vid & 7) * 4;
            float4 x = *(const float4*)(f + (size_t)(n0 + row) * CC + cc + c4);
            fs [c4+0][row] = x.x;     fs [c4+1][row] = x.y;
            fs [c4+2][row] = x.z;     fs [c4+3][row] = x.w;
            f2s[c4+0][row] = x.x*x.x; f2s[c4+1][row] = x.y*x.y;
            f2s[c4+2][row] = x.z*x.z; f2s[c4+3][row] = x.w*x.w;
        }
        // load A/B chunk [32 c x 64 k] — contiguous copy
        #pragma unroll
        for (int v = 0; v < 2; v++) {
            int vid = t + v * 256;          // 512 float4 per array
            ((float4*)As)[vid] = ((const float4*)(g_At + cc * KK))[vid];
            ((float4*)Bs)[vid] = ((const float4*)(g_Bt + cc * KK))[vid];
        }
        __syncthreads();

        #pragma unroll
        for (int c = 0; c < 32; c++) {
            float4 a4  = *(const float4*)&As [c][kx];
            float4 b4  = *(const float4*)&Bs [c][kx];
            float4 fv4 = *(const float4*)&fs [c][ny];
            float4 f24 = *(const float4*)&f2s[c][ny];
            float av[4] = {a4.x, a4.y, a4.z, a4.w};
            float bv[4] = {b4.x, b4.y, b4.z, b4.w};
            float fv[4] = {fv4.x, fv4.y, fv4.z, fv4.w};
            float f2[4] = {f24.x, f24.y, f24.z, f24.w};
            #pragma unroll
            for (int i = 0; i < 4; i++)
                #pragma unroll
                for (int j = 0; j < 4; j++) {
                    acc1[i][j] = fmaf(f2[i], av[j], acc1[i][j]);
                    acc2[i][j] = fmaf(fv[i], bv[j], acc2[i][j]);
                }
        }
        __syncthreads();
    }

    int lnz = 0;
    #pragma unroll
    for (int i = 0; i < 4; i++) {
        int n = n0 + ny + i;
        #pragma unroll
        for (int j = 0; j < 4; j++) {
            int k = kx + j;
            float d = -(acc1[i][j] - 2.0f * acc2[i][j] + g_t3[k]);
            float p = expf(d);
            if (isI) p *= weights[k];
            phi[(size_t)n * KK + k] = p;
            lnz |= (p != 0.0f);
        }
    }
    if (lnz) s_nz = 1;          // benign race: all writers store 1
    __syncthreads();
    if (t == 0) g_nz[isI ? 0 : 1][blockIdx.x] = s_nz;
}

// ---------------------------------------------------------------------------
// GEMM: out[n,m] = sum_k phi_i[n,k] * phi_j[m,k].  64x64 tiles, 256 threads,
// 4x4 per-thread micro-tile. Fast path: if either row-block is all-zero the
// tile is exactly zero -> write zeros without loading phi (exact for fp32).
// ---------------------------------------------------------------------------
__global__ __launch_bounds__(256)
void gemm_kernel(float* __restrict__ out) {
    const int bm = blockIdx.y;   // phi_i row block (output rows)
    const int bn = blockIdx.x;   // phi_j row block (output cols)
    const int t  = threadIdx.x;
    const int txm = (t & 15) * 4;   // local col base
    const int tyn = (t >> 4) * 4;   // local row base

    if (g_nz[0][bm] == 0 || g_nz[1][bn] == 0) {
        float4 z = make_float4(0.f, 0.f, 0.f, 0.f);
        #pragma unroll
        for (int i = 0; i < 4; i++) {
            size_t row = (size_t)(bm * 64 + tyn + i);
            *(float4*)(out + row * NN + bn * 64 + txm) = z;
        }
        return;
    }

    __shared__ float As[64][68];   // [k][n_local]
    __shared__ float Bs[64][68];   // [k][m_local]
    #pragma unroll
    for (int v = 0; v < 4; v++) {
        int vid = t + v * 256;       // 1024 float4 slots per tile
        int row = vid >> 4;          // 16 float4 per 64-wide row
        int k4  = (vid & 15) * 4;
        float4 a = *(const float4*)(g_phi_i + (size_t)(bm * 64 + row) * KK + k4);
        As[k4+0][row] = a.x; As[k4+1][row] = a.y; As[k4+2][row] = a.z; As[k4+3][row] = a.w;
        float4 b = *(const float4*)(g_phi_j + (size_t)(bn * 64 + row) * KK + k4);
        Bs[k4+0][row] = b.x; Bs[k4+1][row] = b.y; Bs[k4+2][row] = b.z; Bs[k4+3][row] = b.w;
    }
    __syncthreads();

    float acc[4][4];
    #pragma unroll
    for (int i = 0; i < 4; i++)
        #pragma unroll
        for (int j = 0; j < 4; j++) acc[i][j] = 0.f;

    #pragma unroll 8
    for (int k = 0; k < 64; k++) {
        float4 a4 = *(const float4*)&As[k][tyn];
        float4 b4 = *(const float4*)&Bs[k][txm];
        float av[4] = {a4.x, a4.y, a4.z, a4.w};
        float bv[4] = {b4.x, b4.y, b4.z, b4.w};
        #pragma unroll
        for (int i = 0; i < 4; i++)
            #pragma unroll
            for (int j = 0; j < 4; j++)
                acc[i][j] = fmaf(av[i], bv[j], acc[i][j]);
    }

    #pragma unroll
    for (int i = 0; i < 4; i++) {
        size_t row = (size_t)(bm * 64 + tyn + i);
        *(float4*)(out + row * NN + bn * 64 + txm) =
            make_float4(acc[i][0], acc[i][1], acc[i][2], acc[i][3]);
    }
}

// ---------------------------------------------------------------------------
extern "C" void kernel_launch(void* const* d_in, const int* in_sizes, int n_in,
                              void* d_out, int out_size) {
    const float* f_i     = (const float*)d_in[0];
    const float* f_j     = (const float*)d_in[1];
    const float* means   = (const float*)d_in[2];
    const float* scales  = (const float*)d_in[3];
    const float* weights = (const float*)d_in[4];
    float* out = (float*)d_out;

    prep_kernel<<<KK, 128>>>(means, scales);
    phi_kernel<<<dim3(NBLK, 2), 256>>>(f_i, f_j, weights);
    gemm_kernel<<<dim3(NBLK, NBLK), 256>>>(out);
}